// round 15
// baseline (speedup 1.0000x reference)
#include <cuda_runtime.h>
#include <cuda_bf16.h>

// Problem constants (SpatialAwareGATConv): N=50000, E=800000, IN_CH=256,
// EDGE_DIM=32, H=4, C=32, HC=128.
#define MAXN 50000
#define MAXE 800000
#define INCH 256
#define EDIM 32
#define HC   128
#define NH   4

// ---------------- scratch (static __device__, no allocations) ----------------
static __device__ float    g_xsrc[(size_t)MAXN * HC];   // x @ W_src   [N,128]
static __device__ float    g_xdst[(size_t)MAXN * HC];   // x @ W_dst   [N,128]
static __device__ float    g_alpha[(size_t)MAXE * NH];  // decayed logits -> ea
static __device__ float    g_s[(size_t)MAXN * NH];      // segment sums
static __device__ unsigned g_m[(size_t)MAXN * NH];      // segment max (encoded)
static __device__ int      g_src[MAXE];
static __device__ int      g_dst[MAXE];
static __device__ int      g_is64;

// ---------------- helpers ----------------
__device__ __forceinline__ unsigned long long d_fma2(unsigned long long a,
                                                     unsigned long long b,
                                                     unsigned long long c) {
    unsigned long long r;
    asm("fma.rn.f32x2 %0, %1, %2, %3;" : "=l"(r) : "l"(a), "l"(b), "l"(c));
    return r;
}
__device__ __forceinline__ unsigned long long d_dup(float x) {
    unsigned long long r;
    unsigned xi = __float_as_uint(x);
    asm("mov.b64 %0, {%1, %1};" : "=l"(r) : "r"(xi));
    return r;
}
__device__ __forceinline__ void d_unpack(unsigned long long v, float& a, float& b) {
    unsigned lo, hi;
    asm("mov.b64 {%0, %1}, %2;" : "=r"(lo), "=r"(hi) : "l"(v));
    a = __uint_as_float(lo);
    b = __uint_as_float(hi);
}
// order-preserving float<->uint encoding for atomicMax
__device__ __forceinline__ unsigned enc_f(float f) {
    unsigned u = __float_as_uint(f);
    return (u & 0x80000000u) ? ~u : (u | 0x80000000u);
}
__device__ __forceinline__ float dec_f(unsigned u) {
    unsigned b = (u & 0x80000000u) ? (u & 0x7fffffffu) : ~u;
    return __uint_as_float(b);
}
// exact identity tanh(x) = 1 - 2/(e^{2x}+1); saturates correctly at +-1
__device__ __forceinline__ float fast_tanh(float x) {
    float e = __expf(2.0f * x);
    return 1.0f - __fdividef(2.0f, e + 1.0f);
}
__device__ __forceinline__ void red_add_v4(float* p, float a, float b, float c, float d) {
    asm volatile("red.global.add.v4.f32 [%0], {%1, %2, %3, %4};"
                 :: "l"(p), "f"(a), "f"(b), "f"(c), "f"(d) : "memory");
}

// ---------------- kernel 0: detect int64 vs int32 edge_index ----------------
__global__ void k_detect(const unsigned* __restrict__ w) {
    __shared__ int nz;
    if (threadIdx.x == 0) nz = 0;
    __syncthreads();
    // odd 32-bit words: high halves if int64 (all zero for values < 2^31)
    unsigned v = w[2 * threadIdx.x + 1];
    if (v != 0u) atomicOr(&nz, 1);
    __syncthreads();
    if (threadIdx.x == 0) g_is64 = (nz == 0) ? 1 : 0;
}

// ---------------- kernel 1: normalize indices to int32 ----------------
__global__ void k_convert(const void* __restrict__ ei, int E) {
    int e = blockIdx.x * blockDim.x + threadIdx.x;
    if (e >= E) return;
    int s, d;
    if (g_is64) {
        const long long* p = (const long long*)ei;
        s = (int)p[e];
        d = (int)p[(size_t)E + e];
    } else {
        const int* p = (const int*)ei;
        s = p[e];
        d = p[E + e];
    }
    g_src[e] = s;
    g_dst[e] = d;
}

// ---------------- kernel 2: init out / stats ----------------
__global__ void k_init(float* __restrict__ outO, int N) {
    int idx = blockIdx.x * blockDim.x + threadIdx.x;
    if (idx < N * HC) outO[idx] = 0.0f;
    if (idx < N * NH) {
        g_s[idx] = 0.0f;
        g_m[idx] = 0u;  // encoded minimum
    }
}

// ---------------- kernel 3: fused node GEMM (x@W_src and x@W_dst) ----------------
// tile: 32 rows x 128 cols, K=256 in chunks of 32. f32x2 packed FMA.
__global__ void __launch_bounds__(256) k_node_gemm(const float* __restrict__ x,
                                                   const float* __restrict__ Ws,
                                                   const float* __restrict__ Wd,
                                                   int N) {
    __shared__ float xs[32][36];   // padded row stride (144B, 16B aligned)
    __shared__ float ws[32][HC];
    __shared__ float wd[32][HC];
    const int tid  = threadIdx.x;
    const int col4 = (tid & 31) * 4;    // 4 consecutive output cols
    const int r0   = (tid >> 5) * 4;    // 4 rows
    const int row0 = blockIdx.x * 32;
    const int lrow = tid >> 3;
    const int lc   = (tid & 7) * 4;

    unsigned long long aS[4][2] = {};
    unsigned long long aD[4][2] = {};

    for (int kc = 0; kc < 8; kc++) {
        float4 xv = make_float4(0.f, 0.f, 0.f, 0.f);
        int grow = row0 + lrow;
        if (grow < N)
            xv = *(const float4*)(x + (size_t)grow * INCH + kc * 32 + lc);
        *(float4*)&xs[lrow][lc] = xv;
#pragma unroll
        for (int i = 0; i < 4; i++) {
            int fi = tid + i * 256;          // 1024 float4s total
            int d  = fi >> 5;
            int cw = (fi & 31) * 4;
            *(float4*)&ws[d][cw] = *(const float4*)(Ws + (size_t)(kc * 32 + d) * HC + cw);
            *(float4*)&wd[d][cw] = *(const float4*)(Wd + (size_t)(kc * 32 + d) * HC + cw);
        }
        __syncthreads();
#pragma unroll
        for (int d = 0; d < 32; d++) {
            ulonglong2 bs = *(const ulonglong2*)&ws[d][col4];
            ulonglong2 bd = *(const ulonglong2*)&wd[d][col4];
#pragma unroll
            for (int r = 0; r < 4; r++) {
                unsigned long long a2 = d_dup(xs[r0 + r][d]);
                aS[r][0] = d_fma2(a2, bs.x, aS[r][0]);
                aS[r][1] = d_fma2(a2, bs.y, aS[r][1]);
                aD[r][0] = d_fma2(a2, bd.x, aD[r][0]);
                aD[r][1] = d_fma2(a2, bd.y, aD[r][1]);
            }
        }
        __syncthreads();
    }
#pragma unroll
    for (int r = 0; r < 4; r++) {
        int grow = row0 + r0 + r;
        if (grow < N) {
            ulonglong2 v;
            v.x = aS[r][0]; v.y = aS[r][1];
            *(ulonglong2*)&g_xsrc[(size_t)grow * HC + col4] = v;
            v.x = aD[r][0]; v.y = aD[r][1];
            *(ulonglong2*)&g_xdst[(size_t)grow * HC + col4] = v;
        }
    }
}

// ---------------- kernel 4: edge pass A ----------------
// warp handles 8 edges; lane owns 4 consecutive channels (c4 = lane*4, head = lane/8).
// Fuses e_feat = edge_attr @ W_edge (register mini-GEMM with shuffled A), tanh,
// attention dot, head reduction, spatial decay, atomic segment-max.
__global__ void __launch_bounds__(256) k_edge_alpha(const float* __restrict__ edge_attr,
                                                    const float* __restrict__ dist_weight,
                                                    const float* __restrict__ W_edge,
                                                    const float* __restrict__ att,
                                                    const float* __restrict__ sscale,
                                                    float* __restrict__ outRaw,
                                                    int E) {
    __shared__ float wsm[EDIM][HC];   // 16 KB
    __shared__ float attsm[HC];
    __shared__ float sssm[NH];
    const int tid = threadIdx.x;
#pragma unroll
    for (int i = 0; i < 4; i++) {
        int fi = tid + i * 256;       // 1024 float4s = 4096 floats
        ((float4*)&wsm[0][0])[fi] = ((const float4*)W_edge)[fi];
    }
    if (tid < HC) attsm[tid] = att[tid];
    if (tid < NH) sssm[tid] = sscale[tid];
    __syncthreads();

    const int w     = tid >> 5;
    const int lane  = tid & 31;
    const int c4    = lane * 4;
    const int h     = lane >> 3;
    const int ebase = blockIdx.x * 64 + w * 8;

    float areg[8];
#pragma unroll
    for (int i = 0; i < 8; i++) {
        int e = ebase + i;
        areg[i] = (e < E) ? edge_attr[(size_t)e * EDIM + lane] : 0.0f;
    }

    unsigned long long ef[8][2] = {};
#pragma unroll
    for (int d = 0; d < EDIM; d++) {
        ulonglong2 b = *(const ulonglong2*)&wsm[d][c4];
#pragma unroll
        for (int i = 0; i < 8; i++) {
            float av = __shfl_sync(0xffffffffu, areg[i], d);
            unsigned long long a2 = d_dup(av);
            ef[i][0] = d_fma2(a2, b.x, ef[i][0]);
            ef[i][1] = d_fma2(a2, b.y, ef[i][1]);
        }
    }

    const float4 attv = *(const float4*)&attsm[c4];
    const float  ssh  = sssm[h];

#pragma unroll
    for (int i = 0; i < 8; i++) {
        int e = ebase + i;
        if (e < E) {  // warp-uniform guard
            int src = g_src[e];
            int dst = g_dst[e];
            float4 xsv = *(const float4*)&g_xsrc[(size_t)src * HC + c4];
            float4 xdv = *(const float4*)&g_xdst[(size_t)dst * HC + c4];
            float f0, f1, f2, f3;
            d_unpack(ef[i][0], f0, f1);
            d_unpack(ef[i][1], f2, f3);
            float p = fast_tanh(xsv.x + xdv.x + f0) * attv.x
                    + fast_tanh(xsv.y + xdv.y + f1) * attv.y
                    + fast_tanh(xsv.z + xdv.z + f2) * attv.z
                    + fast_tanh(xsv.w + xdv.w + f3) * attv.w;
            // reduce across the 8 lanes of this head
            p += __shfl_xor_sync(0xffffffffu, p, 1);
            p += __shfl_xor_sync(0xffffffffu, p, 2);
            p += __shfl_xor_sync(0xffffffffu, p, 4);
            if ((lane & 7) == 0) {
                if (outRaw) outRaw[(size_t)e * NH + h] = p;
                float dw = dist_weight[e];
                float a  = p * __powf(dw, ssh);
                g_alpha[(size_t)e * NH + h] = a;
                atomicMax(&g_m[dst * NH + h], enc_f(a));
            }
        }
    }
}

// ---------------- kernel 5: exp + segment sum ----------------
__global__ void __launch_bounds__(256) k_stats(int E) {
    int idx = blockIdx.x * blockDim.x + threadIdx.x;
    if (idx >= E * NH) return;
    int e = idx >> 2;
    int h = idx & 3;
    int dst = g_dst[e];
    float m  = dec_f(g_m[dst * NH + h]);
    float ea = __expf(g_alpha[idx] - m);
    g_alpha[idx] = ea;
    atomicAdd(&g_s[dst * NH + h], ea);
}

// ---------------- kernel 6: normalize + weighted scatter aggregation ----------------
__global__ void __launch_bounds__(256) k_agg(float* __restrict__ outO,
                                             float* __restrict__ outNorm,
                                             int E) {
    int gw = blockIdx.x * 8 + (threadIdx.x >> 5);  // one warp per edge
    if (gw >= E) return;                            // warp-uniform
    const int lane = threadIdx.x & 31;
    const int c4   = lane * 4;
    const int h    = lane >> 3;
    const int e    = gw;
    int src = g_src[e];
    int dst = g_dst[e];
    float ea   = g_alpha[(size_t)e * NH + h];
    float s    = g_s[dst * NH + h];
    float norm = __fdividef(ea, s + 1e-8f);
    if (outNorm && (lane & 7) == 0) outNorm[(size_t)e * NH + h] = norm;
    float4 xs = *(const float4*)&g_xsrc[(size_t)src * HC + c4];
    red_add_v4(&outO[(size_t)dst * HC + c4],
               xs.x * norm, xs.y * norm, xs.z * norm, xs.w * norm);
}

// ---------------- launch ----------------
extern "C" void kernel_launch(void* const* d_in, const int* in_sizes, int n_in,
                              void* d_out, int out_size) {
    const float* x     = (const float*)d_in[0];
    const void*  ei    = d_in[1];
    const float* eattr = (const float*)d_in[2];
    const float* dw    = (const float*)d_in[3];
    const float* Wsrc  = (const float*)d_in[4];
    const float* Wdst  = (const float*)d_in[5];
    const float* Wedge = (const float*)d_in[6];
    const float* att   = (const float*)d_in[7];
    const float* ss    = (const float*)d_in[8];

    const int N = in_sizes[0] / INCH;
    const int E = in_sizes[3];  // dist_weight has exactly E elements

    float* outO    = (float*)d_out;
    float* outNorm = nullptr;
    float* outRaw  = nullptr;
    long long base = (long long)N * HC;
    if ((long long)out_size >= base + (long long)E * NH)
        outNorm = outO + base;
    if ((long long)out_size >= base + (long long)E * NH * 2)
        outRaw = outO + base + (long long)E * NH;

    k_detect<<<1, 256>>>((const unsigned*)ei);
    k_convert<<<(E + 255) / 256, 256>>>(ei, E);
    k_init<<<(N * HC + 255) / 256, 256>>>(outO, N);
    k_node_gemm<<<(N + 31) / 32, 256>>>(x, Wsrc, Wdst, N);
    k_edge_alpha<<<(E + 63) / 64, 256>>>(eattr, dw, Wedge, att, ss, outRaw, E);
    k_stats<<<(E * NH + 255) / 256, 256>>>(E);
    k_agg<<<(E + 7) / 8, 256>>>(outO, outNorm, E);
}